// round 15
// baseline (speedup 1.0000x reference)
#include <cuda_runtime.h>
#include <cuda_bf16.h>

// PermutationClosedLayer via complement algebra:
//   out[s,r,o] = base[s,o] + sum_{p in comb5(r)} y[s,p,o]
//   y[s,p,o]   = sum_c x[s,p,c] * (W0-W1)[o,c]
//   base[s,o]  = sum_c (sum_p x[s,p,c]) * W1[o,c]
//
// Width-4 mapping: warp covers 4 samples; each lane owns 4 consecutive
// channels of one sample (lane>>3 -> sample, (lane&7)*4 -> channel).
// Output stores are st.global.wt.v4.f32 (STG.128 write-through): the
// 132MB output is write-once/never-read and the replay period is gated
// by DRAM write drain (~4.26 TB/s sustained with .cs). Write-through
// starts the drain immediately instead of accumulating dirty L2 lines
// that trail the kernel window.
// Combination list split per sample (i==0 -> first 126, i>=1 -> rest).
// Block = 256 thr = 8 warps = 4 quads x 2 halves = 16 samples. Grid = 256.

#define NSAMPLES 4096
#define NSIZE 10
#define NCIN 32
#define NCOUT 32
#define NCOMB 252
#define THREADS 256
#define SAMPLES_PER_BLOCK 16

struct f4 { float x, y, z, w; };
__device__ __forceinline__ f4 f4add(f4 a, f4 b) {
    return {a.x + b.x, a.y + b.y, a.z + b.z, a.w + b.w};
}

__device__ __forceinline__ void stg_wt_f4(float* p, f4 v) {
    asm volatile("st.global.wt.v4.f32 [%0], {%1, %2, %3, %4};"
                 :: "l"(p), "f"(v.x), "f"(v.y), "f"(v.z), "f"(v.w) : "memory");
}

// Emit the lexicographic nest restricted to i in [I0, I1]; r is an unroll
// constant at each leaf so skipped subtrees are dead-code-eliminated.
template<int I0, int I1>
__device__ __forceinline__ void emit_half(float* __restrict__ op,
                                          const f4 (&y)[NSIZE], f4 base) {
    int r = 0;
#pragma unroll
    for (int i = 0; i <= 5; i++) {
        const f4 a1 = f4add(base, y[i]);
#pragma unroll
        for (int j = i + 1; j <= 6; j++) {
            const f4 a2 = f4add(a1, y[j]);
#pragma unroll
            for (int k = j + 1; k <= 7; k++) {
                const f4 a3 = f4add(a2, y[k]);
#pragma unroll
                for (int l = k + 1; l <= 8; l++) {
                    const f4 a4 = f4add(a3, y[l]);
#pragma unroll
                    for (int m = l + 1; m <= 9; m++) {
                        if (i >= I0 && i <= I1)
                            stg_wt_f4(op + r * NCOUT, f4add(a4, y[m]));
                        r++;
                    }
                }
            }
        }
    }
}

__global__ __launch_bounds__(THREADS) void pcl_kernel(
    const float* __restrict__ x,    // [S, 10, 32]
    const float* __restrict__ W,    // [2, 32, 32]
    float* __restrict__ out)        // [S, 252, 32]
{
    __shared__ float wd_sm[NCIN][NCOUT];                        // (W0-W1)^T: wd[c][o]
    __shared__ float w1_sm[NCIN][NCOUT];                        // W1^T
    __shared__ float xs[SAMPLES_PER_BLOCK][NSIZE][NCIN + 1];    // padded rows

    const int tid  = threadIdx.x;
    const int lane = tid & 31;
    const int w    = tid >> 5;            // warp 0..7
    const int quad = w & 3;               // sample-quad within block
    const int half = w >> 2;              // 0: combos with pos 0, 1: rest
    const int smp  = quad * 4 + (lane >> 3);     // sample slot 0..15
    const int ch   = (lane & 7) * 4;             // first of 4 channels (16B aligned)

    // Load W (transposed) into shared
    for (int i = tid; i < NCOUT * NCIN; i += THREADS) {
        int o = i >> 5;
        int c = i & 31;
        float w0v = W[o * NCIN + c];
        float w1v = W[NCOUT * NCIN + o * NCIN + c];
        wd_sm[c][o] = w0v - w1v;
        w1_sm[c][o] = w1v;
    }

    const int s_base = blockIdx.x * SAMPLES_PER_BLOCK;

    // half==0 warps stage their quad's 4 samples (coalesced 128B rows)
    if (half == 0) {
#pragma unroll
        for (int t = 0; t < 4; t++) {
            const int ss = quad * 4 + t;
            const float* xp = x + (size_t)(s_base + ss) * (NSIZE * NCIN);
#pragma unroll
            for (int p = 0; p < NSIZE; p++)
                xs[ss][p][lane] = xp[p * NCIN + lane];
        }
    }
    __syncthreads();

    // y[p] = x[smp,p,:] . wd[:,ch..ch+3] ; base = total . w1[:,ch..ch+3]
    f4 y[NSIZE];
#pragma unroll
    for (int p = 0; p < NSIZE; p++) y[p] = {0.f, 0.f, 0.f, 0.f};
    f4 base = {0.f, 0.f, 0.f, 0.f};

#pragma unroll
    for (int c = 0; c < NCIN; c++) {
        const float4 wd4 = *(const float4*)&wd_sm[c][ch];   // ld.shared.v4
        const float4 w14 = *(const float4*)&w1_sm[c][ch];
        float tot = 0.0f;
#pragma unroll
        for (int p = 0; p < NSIZE; p++) {
            const float xv = xs[smp][p][c];   // 4 addrs/warp, distinct banks
            y[p].x = fmaf(xv, wd4.x, y[p].x);
            y[p].y = fmaf(xv, wd4.y, y[p].y);
            y[p].z = fmaf(xv, wd4.z, y[p].z);
            y[p].w = fmaf(xv, wd4.w, y[p].w);
            tot += xv;
        }
        base.x = fmaf(tot, w14.x, base.x);
        base.y = fmaf(tot, w14.y, base.y);
        base.z = fmaf(tot, w14.z, base.z);
        base.w = fmaf(tot, w14.w, base.w);
    }

    // Emit this warp's half of the 252 combinations as write-through STG.128
    float* op = out + (size_t)(s_base + smp) * (size_t)(NCOMB * NCOUT) + ch;
    if (half == 0)
        emit_half<0, 0>(op, y, base);    // r in [0, 126)
    else
        emit_half<1, 5>(op, y, base);    // r in [126, 252)
}

extern "C" void kernel_launch(void* const* d_in, const int* in_sizes, int n_in,
                              void* d_out, int out_size) {
    const float* x = (const float*)d_in[0];
    const float* W = (const float*)d_in[1];
    // d_in[2] = splits : unused (compile-time lexicographic combination table)
    float* out = (float*)d_out;

    dim3 grid(NSAMPLES / SAMPLES_PER_BLOCK);   // 256 blocks
    pcl_kernel<<<grid, THREADS>>>(x, W, out);
}

// round 16
// speedup vs baseline: 1.0760x; 1.0760x over previous
#include <cuda_runtime.h>
#include <cuda_bf16.h>

// PermutationClosedLayer via complement algebra:
//   out[s,r,o] = base[s,o] + sum_{p in comb5(r)} y[s,p,o]
//   y[s,p,o]   = sum_c x[s,p,c] * (W0-W1)[o,c]
//   base[s,o]  = sum_c (sum_p x[s,p,c]) * W1[o,c]
//
// Width-4 mapping: warp covers 4 samples; each lane owns 4 consecutive
// channels of one sample (lane>>3 -> sample, (lane&7)*4 -> channel).
// Output stores are st.global.cs.v4.f32 (STG.128, evict-first streaming):
// the 132MB output is write-once/never-read; .cs lets L2 rate-match the
// DRAM drain in full-line bursts while marking lines for early eviction.
// (Measured: .cs 31.0us < .wt 33.1us < default 34.8us e2e — the replay
// period is gated by sustained HBM write drain at ~4.26 TB/s.)
// Combination list split per sample (i==0 -> first 126, i>=1 -> rest).
// Block = 256 thr = 8 warps = 4 quads x 2 halves = 16 samples. Grid = 256.

#define NSAMPLES 4096
#define NSIZE 10
#define NCIN 32
#define NCOUT 32
#define NCOMB 252
#define THREADS 256
#define SAMPLES_PER_BLOCK 16

struct f4 { float x, y, z, w; };
__device__ __forceinline__ f4 f4add(f4 a, f4 b) {
    return {a.x + b.x, a.y + b.y, a.z + b.z, a.w + b.w};
}

__device__ __forceinline__ void stg_cs_f4(float* p, f4 v) {
    asm volatile("st.global.cs.v4.f32 [%0], {%1, %2, %3, %4};"
                 :: "l"(p), "f"(v.x), "f"(v.y), "f"(v.z), "f"(v.w) : "memory");
}

// Emit the lexicographic nest restricted to i in [I0, I1]; r is an unroll
// constant at each leaf so skipped subtrees are dead-code-eliminated.
template<int I0, int I1>
__device__ __forceinline__ void emit_half(float* __restrict__ op,
                                          const f4 (&y)[NSIZE], f4 base) {
    int r = 0;
#pragma unroll
    for (int i = 0; i <= 5; i++) {
        const f4 a1 = f4add(base, y[i]);
#pragma unroll
        for (int j = i + 1; j <= 6; j++) {
            const f4 a2 = f4add(a1, y[j]);
#pragma unroll
            for (int k = j + 1; k <= 7; k++) {
                const f4 a3 = f4add(a2, y[k]);
#pragma unroll
                for (int l = k + 1; l <= 8; l++) {
                    const f4 a4 = f4add(a3, y[l]);
#pragma unroll
                    for (int m = l + 1; m <= 9; m++) {
                        if (i >= I0 && i <= I1)
                            stg_cs_f4(op + r * NCOUT, f4add(a4, y[m]));
                        r++;
                    }
                }
            }
        }
    }
}

__global__ __launch_bounds__(THREADS) void pcl_kernel(
    const float* __restrict__ x,    // [S, 10, 32]
    const float* __restrict__ W,    // [2, 32, 32]
    float* __restrict__ out)        // [S, 252, 32]
{
    __shared__ float wd_sm[NCIN][NCOUT];                        // (W0-W1)^T: wd[c][o]
    __shared__ float w1_sm[NCIN][NCOUT];                        // W1^T
    __shared__ float xs[SAMPLES_PER_BLOCK][NSIZE][NCIN + 1];    // padded rows

    const int tid  = threadIdx.x;
    const int lane = tid & 31;
    const int w    = tid >> 5;            // warp 0..7
    const int quad = w & 3;               // sample-quad within block
    const int half = w >> 2;              // 0: combos with pos 0, 1: rest
    const int smp  = quad * 4 + (lane >> 3);     // sample slot 0..15
    const int ch   = (lane & 7) * 4;             // first of 4 channels (16B aligned)

    // Load W (transposed) into shared
    for (int i = tid; i < NCOUT * NCIN; i += THREADS) {
        int o = i >> 5;
        int c = i & 31;
        float w0v = W[o * NCIN + c];
        float w1v = W[NCOUT * NCIN + o * NCIN + c];
        wd_sm[c][o] = w0v - w1v;
        w1_sm[c][o] = w1v;
    }

    const int s_base = blockIdx.x * SAMPLES_PER_BLOCK;

    // half==0 warps stage their quad's 4 samples (coalesced 128B rows)
    if (half == 0) {
#pragma unroll
        for (int t = 0; t < 4; t++) {
            const int ss = quad * 4 + t;
            const float* xp = x + (size_t)(s_base + ss) * (NSIZE * NCIN);
#pragma unroll
            for (int p = 0; p < NSIZE; p++)
                xs[ss][p][lane] = xp[p * NCIN + lane];
        }
    }
    __syncthreads();

    // y[p] = x[smp,p,:] . wd[:,ch..ch+3] ; base = total . w1[:,ch..ch+3]
    f4 y[NSIZE];
#pragma unroll
    for (int p = 0; p < NSIZE; p++) y[p] = {0.f, 0.f, 0.f, 0.f};
    f4 base = {0.f, 0.f, 0.f, 0.f};

#pragma unroll
    for (int c = 0; c < NCIN; c++) {
        const float4 wd4 = *(const float4*)&wd_sm[c][ch];   // ld.shared.v4
        const float4 w14 = *(const float4*)&w1_sm[c][ch];
        float tot = 0.0f;
#pragma unroll
        for (int p = 0; p < NSIZE; p++) {
            const float xv = xs[smp][p][c];   // 4 addrs/warp, distinct banks
            y[p].x = fmaf(xv, wd4.x, y[p].x);
            y[p].y = fmaf(xv, wd4.y, y[p].y);
            y[p].z = fmaf(xv, wd4.z, y[p].z);
            y[p].w = fmaf(xv, wd4.w, y[p].w);
            tot += xv;
        }
        base.x = fmaf(tot, w14.x, base.x);
        base.y = fmaf(tot, w14.y, base.y);
        base.z = fmaf(tot, w14.z, base.z);
        base.w = fmaf(tot, w14.w, base.w);
    }

    // Emit this warp's half of the 252 combinations as streaming STG.128
    float* op = out + (size_t)(s_base + smp) * (size_t)(NCOMB * NCOUT) + ch;
    if (half == 0)
        emit_half<0, 0>(op, y, base);    // r in [0, 126)
    else
        emit_half<1, 5>(op, y, base);    // r in [126, 252)
}

extern "C" void kernel_launch(void* const* d_in, const int* in_sizes, int n_in,
                              void* d_out, int out_size) {
    const float* x = (const float*)d_in[0];
    const float* W = (const float*)d_in[1];
    // d_in[2] = splits : unused (compile-time lexicographic combination table)
    float* out = (float*)d_out;

    dim3 grid(NSAMPLES / SAMPLES_PER_BLOCK);   // 256 blocks
    pcl_kernel<<<grid, THREADS>>>(x, W, out);
}